// round 12
// baseline (speedup 1.0000x reference)
#include <cuda_runtime.h>

// GraphConv: out = (feat + scatter_sum(feat[src]*norm_l[src] -> dst)) * norm_r
// norm_l = rsqrt(max(out_deg,1)+1), norm_r = rsqrt(max(in_deg,1)+1)
// N=100000 nodes, D=64 f32 features, E=1.25M edges (int32 indices).
//
// CSR-by-dst counting sort + warp-per-node register aggregation.
// R12: aggregate processes 2 edges/iter with 16-lane float4 halves
// (half the load instructions), degree pass int2-vectorized, norm fused
// into the scan epilogue.

#define N_MAX 100000
#define E_MAX 1250000
#define D 64
#define CHUNK 1024
#define BTHREADS 256
#define MAX_BLOCKS 128

__device__ int   g_outdeg[N_MAX];
__device__ int   g_indeg[N_MAX];
__device__ int   g_cursor[N_MAX];
__device__ int   g_row_start[N_MAX + 1];
__device__ int   g_bsum[MAX_BLOCKS];
__device__ float g_norml[N_MAX];
__device__ float g_normr[N_MAX];
__device__ int   g_edge_src[E_MAX];

// ---------------------------------------------------------------------------
// 1) zero degree scratch
// ---------------------------------------------------------------------------
__global__ void k_zero(int n) {
    int stride = gridDim.x * blockDim.x;
    for (int j = blockIdx.x * blockDim.x + threadIdx.x; j < n; j += stride) {
        g_outdeg[j] = 0;
        g_indeg[j]  = 0;
    }
}

// ---------------------------------------------------------------------------
// 2) degree counting, 2 edges per thread (int2 loads, int REDG)
// ---------------------------------------------------------------------------
__global__ void k_degree(const int* __restrict__ src,
                         const int* __restrict__ dst, int E) {
    int i = blockIdx.x * blockDim.x + threadIdx.x;
    int E2 = E >> 1;
    if (i < E2) {
        int2 s = reinterpret_cast<const int2*>(src)[i];
        int2 d = reinterpret_cast<const int2*>(dst)[i];
        atomicAdd(&g_outdeg[s.x], 1);
        atomicAdd(&g_outdeg[s.y], 1);
        atomicAdd(&g_indeg[d.x], 1);
        atomicAdd(&g_indeg[d.y], 1);
    } else if (i == E2 && (E & 1)) {
        atomicAdd(&g_outdeg[src[E - 1]], 1);
        atomicAdd(&g_indeg[dst[E - 1]], 1);
    }
}

// ---------------------------------------------------------------------------
// 3a) scan pass 1: per-block local exclusive scan of indeg (1024/block)
// ---------------------------------------------------------------------------
__global__ void k_scan1(int n) {
    __shared__ int warp_sums[BTHREADS / 32];
    int b = blockIdx.x;
    int t = threadIdx.x;
    int i0 = b * CHUNK + t * 4;

    int v0 = (i0 + 0 < n) ? g_indeg[i0 + 0] : 0;
    int v1 = (i0 + 1 < n) ? g_indeg[i0 + 1] : 0;
    int v2 = (i0 + 2 < n) ? g_indeg[i0 + 2] : 0;
    int v3 = (i0 + 3 < n) ? g_indeg[i0 + 3] : 0;
    int tsum = v0 + v1 + v2 + v3;

    int lane = t & 31, wid = t >> 5;
    int x = tsum;
    #pragma unroll
    for (int off = 1; off < 32; off <<= 1) {
        int y = __shfl_up_sync(0xffffffffu, x, off);
        if (lane >= off) x += y;
    }
    if (lane == 31) warp_sums[wid] = x;
    __syncthreads();
    if (wid == 0) {
        int w = (lane < BTHREADS / 32) ? warp_sums[lane] : 0;
        #pragma unroll
        for (int off = 1; off < BTHREADS / 32; off <<= 1) {
            int y = __shfl_up_sync(0xffffffffu, w, off);
            if (lane >= off) w += y;
        }
        if (lane < BTHREADS / 32) warp_sums[lane] = w;
    }
    __syncthreads();

    int excl = x - tsum + (wid > 0 ? warp_sums[wid - 1] : 0);
    if (i0 + 0 < n) g_row_start[i0 + 0] = excl;
    if (i0 + 1 < n) g_row_start[i0 + 1] = excl + v0;
    if (i0 + 2 < n) g_row_start[i0 + 2] = excl + v0 + v1;
    if (i0 + 3 < n) g_row_start[i0 + 3] = excl + v0 + v1 + v2;
    if (t == BTHREADS - 1) g_bsum[b] = excl + tsum;
}

// ---------------------------------------------------------------------------
// 3b) scan pass 2: exclusive scan of the (<=128) block sums
// ---------------------------------------------------------------------------
__global__ void k_scan2(int nb) {
    __shared__ int warp_sums[4];
    int t = threadIdx.x;            // 128 threads
    int lane = t & 31, wid = t >> 5;
    int v = (t < nb) ? g_bsum[t] : 0;
    int x = v;
    #pragma unroll
    for (int off = 1; off < 32; off <<= 1) {
        int y = __shfl_up_sync(0xffffffffu, x, off);
        if (lane >= off) x += y;
    }
    if (lane == 31) warp_sums[wid] = x;
    __syncthreads();
    if (wid == 0 && lane < 4) {
        int w = warp_sums[lane];
        #pragma unroll
        for (int off = 1; off < 4; off <<= 1) {
            int y = __shfl_up_sync(0x0000000fu, w, off);
            if (lane >= off) w += y;
        }
        warp_sums[lane] = w;
    }
    __syncthreads();
    int incl = x + (wid > 0 ? warp_sums[wid - 1] : 0);
    if (t < nb) g_bsum[t] = incl - v;
}

// ---------------------------------------------------------------------------
// 3c) scan pass 3 + norms: add block offsets, seed cursors, compute norms
// ---------------------------------------------------------------------------
__global__ void k_scan3(int n, int E) {
    int i = blockIdx.x * blockDim.x + threadIdx.x;
    if (i < n) {
        int rs = g_row_start[i] + g_bsum[i >> 10];   // CHUNK = 1024
        g_row_start[i] = rs;
        g_cursor[i] = rs;
        g_norml[i] = rsqrtf(fmaxf((float)g_outdeg[i], 1.0f) + 1.0f);
        g_normr[i] = rsqrtf(fmaxf((float)g_indeg[i], 1.0f) + 1.0f);
    }
    if (i == 0) g_row_start[n] = E;
}

// ---------------------------------------------------------------------------
// 4) fill CSR edge list: bucket src ids by dst (cursor pre-seeded)
// ---------------------------------------------------------------------------
__global__ void k_fill(const int* __restrict__ src,
                       const int* __restrict__ dst, int E) {
    int i = blockIdx.x * blockDim.x + threadIdx.x;
    if (i < E) {
        int pos = atomicAdd(&g_cursor[dst[i]], 1);
        g_edge_src[pos] = src[i];
    }
}

// ---------------------------------------------------------------------------
// 5) aggregate: one warp per dst node, TWO edges per iteration.
//    Lanes 0-15 (half 0) process even-offset edges, lanes 16-31 (half 1)
//    odd-offset edges; each lane gathers one float4 of feat[src]
//    (16 x 16B = 256B coalesced per edge). Halves merged via shfl_xor(16).
//    Single fused store: out = (feat + h) * norm_r. No atomics.
// ---------------------------------------------------------------------------
__global__ void k_aggregate(const float* __restrict__ feat,
                            float* __restrict__ out, int n) {
    int node = (blockIdx.x * blockDim.x + threadIdx.x) >> 5;
    int lane = threadIdx.x & 31;
    if (node >= n) return;

    int half = lane >> 4;        // 0 or 1: which edge of the pair
    int fl   = lane & 15;        // float4 chunk index (cols 4*fl..4*fl+3)

    int beg = g_row_start[node];
    int end = g_row_start[node + 1];

    float ax = 0.f, ay = 0.f, az = 0.f, aw = 0.f;

    int j = beg;
    // 2 pairs (4 edges) per iteration: 2 independent gathers per lane
    for (; j + 4 <= end; j += 4) {
        int e0 = j + half;
        int e1 = j + 2 + half;
        int s0 = __ldg(&g_edge_src[e0]);
        int s1 = __ldg(&g_edge_src[e1]);
        float n0 = __ldg(&g_norml[s0]);
        float n1 = __ldg(&g_norml[s1]);
        float4 v0 = *reinterpret_cast<const float4*>(feat + ((long)s0 << 6) + (fl << 2));
        float4 v1 = *reinterpret_cast<const float4*>(feat + ((long)s1 << 6) + (fl << 2));
        ax += v0.x * n0 + v1.x * n1;
        ay += v0.y * n0 + v1.y * n1;
        az += v0.z * n0 + v1.z * n1;
        aw += v0.w * n0 + v1.w * n1;
    }
    // one remaining pair
    if (j + 2 <= end) {
        int e = j + half;
        int s = __ldg(&g_edge_src[e]);
        float nl = __ldg(&g_norml[s]);
        float4 v = *reinterpret_cast<const float4*>(feat + ((long)s << 6) + (fl << 2));
        ax += v.x * nl; ay += v.y * nl; az += v.z * nl; aw += v.w * nl;
        j += 2;
    }
    // odd leftover edge: processed by half 0 only
    if (j < end && half == 0) {
        int s = __ldg(&g_edge_src[j]);
        float nl = __ldg(&g_norml[s]);
        float4 v = *reinterpret_cast<const float4*>(feat + ((long)s << 6) + (fl << 2));
        ax += v.x * nl; ay += v.y * nl; az += v.z * nl; aw += v.w * nl;
    }

    // merge the two halves (lane L and L^16 hold partial sums of chunk fl)
    ax += __shfl_xor_sync(0xffffffffu, ax, 16);
    ay += __shfl_xor_sync(0xffffffffu, ay, 16);
    az += __shfl_xor_sync(0xffffffffu, az, 16);
    aw += __shfl_xor_sync(0xffffffffu, aw, 16);

    if (half == 0) {
        float nr = g_normr[node];
        float4 f = *reinterpret_cast<const float4*>(feat + ((long)node << 6) + (fl << 2));
        float4 r;
        r.x = (f.x + ax) * nr;
        r.y = (f.y + ay) * nr;
        r.z = (f.z + az) * nr;
        r.w = (f.w + aw) * nr;
        *reinterpret_cast<float4*>(out + ((long)node << 6) + (fl << 2)) = r;
    }
}

extern "C" void kernel_launch(void* const* d_in, const int* in_sizes, int n_in,
                              void* d_out, int out_size) {
    const float* feat = (const float*)d_in[0];
    const int*   src  = (const int*)d_in[1];
    const int*   dst  = (const int*)d_in[2];
    float*       out  = (float*)d_out;

    int n = in_sizes[0] / D;      // 100000
    int E = in_sizes[1];          // 1250000
    int nb = (n + CHUNK - 1) / CHUNK;   // 98 scan blocks
    int E2 = (E >> 1) + 1;              // degree threads (2 edges each + tail)

    k_zero<<<256, 256>>>(n);
    k_degree<<<(E2 + 255) / 256, 256>>>(src, dst, E);
    k_scan1<<<nb, BTHREADS>>>(n);
    k_scan2<<<1, 128>>>(nb);
    k_scan3<<<(n + 255) / 256, 256>>>(n, E);
    k_fill<<<(E + 255) / 256, 256>>>(src, dst, E);
    {
        long long threads = (long long)n * 32;
        int blocks = (int)((threads + 255) / 256);
        k_aggregate<<<blocks, 256>>>(feat, out, n);
    }
}